// round 1
// baseline (speedup 1.0000x reference)
#include <cuda_runtime.h>
#include <math.h>

#define BN   16
#define DD   768
#define NN   1024
#define ZZ   256
#define TK   512

// -------- scratch (device globals; no allocation allowed) --------
__device__ float g_score[BN*NN];
__device__ float g_mu[BN*NN];
__device__ float g_rstd[BN*NN];
__device__ int   g_topidx[BN*TK];
__device__ int   g_mask[BN*NN];
__device__ float g_bmin[BN];
__device__ float g_bmax[BN];
__device__ float g_W[DD*ZZ];       // W[d,o] = sum_z wp[d,z]*conv_w[o,z]
__device__ float g_c0[ZZ];         // conv_w@bp + conv_b   (top columns bias)
__device__ float g_c1[ZZ];         // conv_w@mask_token + conv_b (non-top columns)

// =================================================================
// K1: x = transpose(image_features); h = relu(x@w1+b1);
//     score = sigmoid(h@w2+b2); also per-token mean / rstd of x.
// Tile: 64 tokens x 128 cols, threads 256 (8x32), thread tile 8x4.
// x tile resident in smem (64x769), w1 streamed in 32-k chunks.
// =================================================================
__global__ void __launch_bounds__(256, 1)
k1_gemm_score(const float* __restrict__ IF, const float* __restrict__ w1,
              const float* __restrict__ b1, const float* __restrict__ w2,
              const float* __restrict__ b2)
{
    extern __shared__ float sm[];
    float*  xs  = sm;                      // 64 * 769 floats
    float4* ws4 = (float4*)(sm + 64*769);  // 32 k x 128 e  (as float4)

    const int tid = threadIdx.x;
    const int ty  = tid >> 5;    // 0..7  -> token group
    const int tx  = tid & 31;    // 0..31 -> e group
    const int b   = blockIdx.x >> 4;
    const int n0  = (blockIdx.x & 15) << 6;

    // ---- load x tile (transpose on the fly), vectorized ----
    const float4* base4 = (const float4*)(IF + (size_t)b * DD * NN);
    const int n04 = n0 >> 2;
    for (int v = tid; v < 64*768/4; v += 256) {
        int d  = v >> 4;
        int t4 = v & 15;
        float4 f = base4[(size_t)d*256 + n04 + t4];
        int t = t4 * 4;
        xs[(t+0)*769 + d] = f.x;
        xs[(t+1)*769 + d] = f.y;
        xs[(t+2)*769 + d] = f.z;
        xs[(t+3)*769 + d] = f.w;
    }
    __syncthreads();

    // ---- per-token mean / rstd (warp ty handles tokens ty*8..ty*8+7) ----
    for (int i = 0; i < 8; ++i) {
        int t = ty*8 + i;
        const float* xrow = xs + t*769;
        float s = 0.f, ss = 0.f;
        for (int d = tx; d < 768; d += 32) { float v = xrow[d]; s += v; ss = fmaf(v, v, ss); }
        for (int off = 16; off; off >>= 1) {
            s  += __shfl_xor_sync(0xffffffffu, s,  off);
            ss += __shfl_xor_sync(0xffffffffu, ss, off);
        }
        if (tx == 0) {
            float mu  = s * (1.0f/768.0f);
            float var = ss * (1.0f/768.0f) - mu*mu;
            g_mu  [b*NN + n0 + t] = mu;
            g_rstd[b*NN + n0 + t] = rsqrtf(var + 1e-5f);
        }
    }

    float sacc[8];
    #pragma unroll
    for (int i = 0; i < 8; ++i) sacc[i] = 0.f;

    const float* xr[8];
    #pragma unroll
    for (int i = 0; i < 8; ++i) xr[i] = xs + (ty*8 + i)*769;

    for (int ec = 0; ec < 6; ++ec) {
        float acc[8][4];
        #pragma unroll
        for (int i = 0; i < 8; ++i)
            #pragma unroll
            for (int j = 0; j < 4; ++j) acc[i][j] = 0.f;

        for (int kt = 0; kt < 24; ++kt) {
            const float4* w1v = (const float4*)(w1 + (size_t)(kt*32)*768 + ec*128);
            #pragma unroll
            for (int q = 0; q < 4; ++q) {
                int v  = tid + q*256;
                int kk = v >> 5, e4 = v & 31;
                ws4[kk*32 + e4] = w1v[(size_t)kk*192 + e4];
            }
            __syncthreads();
            const int kb = kt*32;
            #pragma unroll
            for (int kk = 0; kk < 32; ++kk) {
                float4 wv = ws4[kk*32 + tx];
                #pragma unroll
                for (int i = 0; i < 8; ++i) {
                    float xv = xr[i][kb + kk];
                    acc[i][0] = fmaf(xv, wv.x, acc[i][0]);
                    acc[i][1] = fmaf(xv, wv.y, acc[i][1]);
                    acc[i][2] = fmaf(xv, wv.z, acc[i][2]);
                    acc[i][3] = fmaf(xv, wv.w, acc[i][3]);
                }
            }
            __syncthreads();
        }
        // epilogue: relu + contract with w2
        #pragma unroll
        for (int j = 0; j < 4; ++j) {
            int e = ec*128 + tx*4 + j;
            float bb  = b1[e];
            float wv2 = w2[e];
            #pragma unroll
            for (int i = 0; i < 8; ++i) {
                float h = fmaxf(acc[i][j] + bb, 0.0f);
                sacc[i] = fmaf(h, wv2, sacc[i]);
            }
        }
    }

    #pragma unroll
    for (int i = 0; i < 8; ++i)
        for (int off = 16; off; off >>= 1)
            sacc[i] += __shfl_xor_sync(0xffffffffu, sacc[i], off);
    if (tx == 0) {
        float bias2 = b2[0];
        for (int i = 0; i < 8; ++i) {
            float s = sacc[i] + bias2;
            g_score[b*NN + n0 + ty*8 + i] = 1.0f / (1.0f + expf(-s));
        }
    }
}

// =================================================================
// K2: per-batch top-512 via bitonic sort of packed keys.
// key = (ordered(score) << 32) | (1023 - n)  -> ascending sort,
// top half = top-512; ties break to lower index (matches stable argsort).
// Produces: g_mask, ascending-compacted g_topidx, per-batch min/max.
// =================================================================
__global__ void k2_topk()
{
    __shared__ unsigned long long keys[1024];
    __shared__ int msk[1024];
    __shared__ int pA[1024];
    __shared__ int pB[1024];
    const int b = blockIdx.x, tid = threadIdx.x;

    for (int i = tid; i < 1024; i += 512) {
        unsigned u = __float_as_uint(g_score[b*NN + i]);
        u = (u & 0x80000000u) ? ~u : (u | 0x80000000u);
        keys[i] = ((unsigned long long)u << 32) | (unsigned)(1023 - i);
    }
    __syncthreads();

    for (int k = 2; k <= 1024; k <<= 1)
        for (int j = k >> 1; j > 0; j >>= 1) {
            for (int i = tid; i < 1024; i += 512) {
                int ixj = i ^ j;
                if (ixj > i) {
                    bool up = ((i & k) == 0);
                    unsigned long long a = keys[i], c = keys[ixj];
                    if ((a > c) == up) { keys[i] = c; keys[ixj] = a; }
                }
            }
            __syncthreads();
        }

    for (int i = tid; i < 1024; i += 512) {
        int n = 1023 - (int)(unsigned)(keys[i] & 0xffffffffull);
        msk[n] = (i >= 512) ? 1 : 0;
    }
    __syncthreads();
    for (int i = tid; i < 1024; i += 512) { g_mask[b*NN + i] = msk[i]; pA[i] = msk[i]; }
    __syncthreads();

    int* src = pA; int* dst = pB;
    for (int off = 1; off < 1024; off <<= 1) {
        for (int i = tid; i < 1024; i += 512)
            dst[i] = src[i] + ((i >= off) ? src[i - off] : 0);
        __syncthreads();
        int* t = src; src = dst; dst = t;
    }
    for (int i = tid; i < 1024; i += 512)
        if (msk[i]) g_topidx[b*TK + src[i] - 1] = i;

    if (tid == 0) {
        unsigned umax = (unsigned)(keys[1023] >> 32);
        unsigned umin = (unsigned)(keys[0]    >> 32);
        g_bmax[b] = (umax & 0x80000000u) ? __uint_as_float(umax ^ 0x80000000u)
                                         : __uint_as_float(~umax);
        g_bmin[b] = (umin & 0x80000000u) ? __uint_as_float(umin ^ 0x80000000u)
                                         : __uint_as_float(~umin);
    }
}

// =================================================================
// K3: W = wp @ conv_w^T  (768x256 · 256x256), tiled 64x64.
// =================================================================
__global__ void k3_W(const float* __restrict__ wp, const float* __restrict__ conv_w)
{
    __shared__ float As[32*68];
    __shared__ float Bs[32*68];
    const int tid = threadIdx.x;
    const int tx  = tid & 15, ty = tid >> 4;
    const int o0  = blockIdx.x * 64;
    const int d0  = blockIdx.y * 64;

    float acc[4][4];
    #pragma unroll
    for (int i = 0; i < 4; ++i)
        #pragma unroll
        for (int j = 0; j < 4; ++j) acc[i][j] = 0.f;

    for (int k0 = 0; k0 < 256; k0 += 32) {
        #pragma unroll
        for (int q = 0; q < 8; ++q) {
            int v = tid + q*256;
            int r = v >> 5, kk = v & 31;
            As[kk*68 + r] = wp    [(size_t)(d0 + r)*256 + k0 + kk];
            Bs[kk*68 + r] = conv_w[(size_t)(o0 + r)*256 + k0 + kk];
        }
        __syncthreads();
        #pragma unroll
        for (int kk = 0; kk < 32; ++kk) {
            float a[4], bb[4];
            #pragma unroll
            for (int i = 0; i < 4; ++i) a[i]  = As[kk*68 + ty*4 + i];
            #pragma unroll
            for (int j = 0; j < 4; ++j) bb[j] = Bs[kk*68 + tx*4 + j];
            #pragma unroll
            for (int i = 0; i < 4; ++i)
                #pragma unroll
                for (int j = 0; j < 4; ++j)
                    acc[i][j] = fmaf(a[i], bb[j], acc[i][j]);
        }
        __syncthreads();
    }
    #pragma unroll
    for (int i = 0; i < 4; ++i)
        #pragma unroll
        for (int j = 0; j < 4; ++j)
            g_W[(size_t)(d0 + ty*4 + i)*256 + o0 + tx*4 + j] = acc[i][j];
}

// =================================================================
// K4: c0 = conv_w@bp + conv_b ; c1 = conv_w@mask_token + conv_b
// =================================================================
__global__ void k4_c(const float* __restrict__ conv_w, const float* __restrict__ bp,
                     const float* __restrict__ mt, const float* __restrict__ conv_b)
{
    int o = threadIdx.x;
    float s0 = 0.f, s1 = 0.f;
    for (int z = 0; z < 256; ++z) {
        float cw = conv_w[o*256 + z];
        s0 = fmaf(cw, bp[z], s0);
        s1 = fmaf(cw, mt[z], s1);
    }
    g_c0[o] = s0 + conv_b[o];
    g_c1[o] = s1 + conv_b[o];
}

// =================================================================
// K5: fill dec with the constant non-top column c1 (top overwritten by K7).
// =================================================================
__global__ void k5_fill(float* __restrict__ dec)
{
    int b = blockIdx.x >> 8, o = blockIdx.x & 255;
    float c = g_c1[o];
    float4 f = make_float4(c, c, c, c);
    float4* row = (float4*)(dec + ((size_t)b*256 + o)*1024);
    row[threadIdx.x] = f;
}

// =================================================================
// K6: binary_map + score_map (nearest upsample x16, global min/max norm)
// =================================================================
__global__ void k6_maps(float* __restrict__ bin, float* __restrict__ scm)
{
    const int b = blockIdx.x >> 9;
    const int y = blockIdx.x & 511;
    float mn = g_bmin[0], mx = g_bmax[0];
    #pragma unroll
    for (int k = 1; k < 16; ++k) { mn = fminf(mn, g_bmin[k]); mx = fmaxf(mx, g_bmax[k]); }
    float inv = 1.0f / fmaxf(mx - mn, 1e-5f);

    const int x = threadIdx.x;
    const int n = (y >> 4)*32 + (x >> 4);
    size_t o = (size_t)b*262144 + (size_t)y*512 + x;
    bin[o] = g_mask[b*NN + n] ? 1.0f : 0.0f;
    scm[o] = (g_score[b*NN + n] - mn) * inv;
}

// =================================================================
// K7: dec top columns:  dec[b,:,n] = ((x-mu)*rstd*score) @ W + c0
// 64 top tokens per block, 256 output cols in two 128-chunks.
// =================================================================
__global__ void __launch_bounds__(256, 1)
k7_dec(const float* __restrict__ IF, float* __restrict__ dec)
{
    extern __shared__ float sm[];
    float*  xs  = sm;                      // 64 x 769
    float4* ws4 = (float4*)(sm + 64*769);  // 32 x 128 of W
    __shared__ int   tok[64];
    __shared__ float mus[64];
    __shared__ float scls[64];

    const int tid = threadIdx.x;
    const int ty  = tid >> 5, tx = tid & 31;
    const int b   = blockIdx.x >> 3;
    const int s0  = (blockIdx.x & 7) << 6;

    if (tid < 64) {
        int t = g_topidx[b*TK + s0 + tid];
        tok[tid]  = t;
        mus[tid]  = g_mu[b*NN + t];
        scls[tid] = g_rstd[b*NN + t] * g_score[b*NN + t];
    }
    __syncthreads();

    const float* base = IF + (size_t)b * DD * NN;
    #pragma unroll 4
    for (int v = tid; v < 64*768; v += 256) {
        int d = v >> 6, t = v & 63;
        float x = base[(size_t)d*1024 + tok[t]];
        xs[t*769 + d] = (x - mus[t]) * scls[t];
    }
    __syncthreads();

    const float* xr[8];
    #pragma unroll
    for (int i = 0; i < 8; ++i) xr[i] = xs + (ty*8 + i)*769;

    for (int oc = 0; oc < 2; ++oc) {
        float acc[8][4];
        #pragma unroll
        for (int i = 0; i < 8; ++i)
            #pragma unroll
            for (int j = 0; j < 4; ++j) acc[i][j] = 0.f;

        for (int kt = 0; kt < 24; ++kt) {
            const float4* wv4 = (const float4*)(g_W + (size_t)(kt*32)*256 + oc*128);
            #pragma unroll
            for (int q = 0; q < 4; ++q) {
                int v  = tid + q*256;
                int kk = v >> 5, e4 = v & 31;
                ws4[kk*32 + e4] = wv4[(size_t)kk*64 + e4];
            }
            __syncthreads();
            const int kb = kt*32;
            #pragma unroll
            for (int kk = 0; kk < 32; ++kk) {
                float4 wv = ws4[kk*32 + tx];
                #pragma unroll
                for (int i = 0; i < 8; ++i) {
                    float xv = xr[i][kb + kk];
                    acc[i][0] = fmaf(xv, wv.x, acc[i][0]);
                    acc[i][1] = fmaf(xv, wv.y, acc[i][1]);
                    acc[i][2] = fmaf(xv, wv.z, acc[i][2]);
                    acc[i][3] = fmaf(xv, wv.w, acc[i][3]);
                }
            }
            __syncthreads();
        }
        #pragma unroll
        for (int j = 0; j < 4; ++j) {
            int o = oc*128 + tx*4 + j;
            float c0 = g_c0[o];
            float* drow = dec + ((size_t)b*256 + o)*1024;
            #pragma unroll
            for (int i = 0; i < 8; ++i)
                drow[tok[ty*8 + i]] = acc[i][j] + c0;
        }
    }
}

// =================================================================
extern "C" void kernel_launch(void* const* d_in, const int* in_sizes, int n_in,
                              void* d_out, int out_size)
{
    const float* IF     = (const float*)d_in[0];
    const float* w1     = (const float*)d_in[1];
    const float* b1     = (const float*)d_in[2];
    const float* w2     = (const float*)d_in[3];
    const float* b2     = (const float*)d_in[4];
    const float* wp     = (const float*)d_in[5];
    const float* bp     = (const float*)d_in[6];
    const float* mt     = (const float*)d_in[7];
    const float* conv_w = (const float*)d_in[8];
    const float* conv_b = (const float*)d_in[9];

    float* out = (float*)d_out;
    float* dec = out;                 // 16*256*1024
    float* bin = out + 4194304;       // 16*1*512*512
    float* scm = out + 8388608;       // 16*1*512*512

    const size_t smem = (size_t)(64*769 + 32*128) * sizeof(float);  // 213248 B
    cudaFuncSetAttribute(k1_gemm_score, cudaFuncAttributeMaxDynamicSharedMemorySize, (int)smem);
    cudaFuncSetAttribute(k7_dec,        cudaFuncAttributeMaxDynamicSharedMemorySize, (int)smem);

    k1_gemm_score<<<256, 256, smem>>>(IF, w1, b1, w2, b2);
    k2_topk<<<16, 512>>>();
    k3_W<<<dim3(4, 12), 256>>>(wp, conv_w);
    k4_c<<<1, 256>>>(conv_w, bp, mt, conv_b);
    k5_fill<<<4096, 256>>>(dec);
    k6_maps<<<8192, 512>>>(bin, scm);
    k7_dec<<<128, 256, smem>>>(IF, dec);
}